// round 15
// baseline (speedup 1.0000x reference)
#include <cuda_runtime.h>
#include <cuda_fp16.h>
#include <cuda_fp8.h>
#include <mma.h>
#include <math.h>

#define NN 50000
#define BB 8
#define EE 800000
#define NB (NN * BB)
#define FM 0xffffffffu
#define YSTR 48

using namespace nvcuda;

__device__ uint4 g_bufA8[NN * 16];
__device__ uint4 g_bufB8[NN * 16];
__device__ float g_h3[NN * BB];
__device__ int   g_degi[NN];
__device__ float g_dinv[NN];
__device__ int   g_rs[NN];
__device__ int   g_re[NN];
__device__ int   g_cur[NN];
__device__ int   g_csrc[EE];
__device__ int   g_total;

__device__ __forceinline__ unsigned short q2(float a, float b) {
    return (unsigned short)__nv_cvt_float2_to_fp8x2(make_float2(a, b), __NV_SATFINITE, __NV_E4M3);
}

__device__ __forceinline__ unsigned short q2h(__half2 v) {
    return (unsigned short)__nv_cvt_halfraw2_to_fp8x2(*reinterpret_cast<__half2_raw*>(&v), __NV_SATFINITE, __NV_E4M3);
}

__global__ __launch_bounds__(256) void count_kernel(const int* __restrict__ ei, float* __restrict__ out) {
    if (blockIdx.x == 0) {
        if (threadIdx.x < BB) out[threadIdx.x] = 0.0f;
        if (threadIdx.x == BB) g_total = 0;
    }
    int e4 = blockIdx.x * 256 + threadIdx.x;
    if (e4 < EE / 4) {
        int4 d = ((const int4*)(ei + EE))[e4];
        atomicAdd(&g_degi[d.x], 1);
        atomicAdd(&g_degi[d.y], 1);
        atomicAdd(&g_degi[d.z], 1);
        atomicAdd(&g_degi[d.w], 1);
    }
}

__global__ __launch_bounds__(256) void seg_kernel() {
    int i = blockIdx.x * 256 + threadIdx.x;
    int lane = threadIdx.x & 31;
    int m = 0;
    if (i < NN) { m = g_degi[i]; g_degi[i] = 0; }
    int incl = m;
    for (int o = 1; o < 32; o <<= 1) {
        int v = __shfl_up_sync(FM, incl, o);
        if (lane >= o) incl += v;
    }
    int base = 0;
    if (lane == 31) base = atomicAdd(&g_total, incl);
    base = __shfl_sync(FM, base, 31);
    if (i < NN) {
        int st = base + incl - m;
        g_rs[i] = st;
        g_re[i] = st + m;
        g_cur[i] = st;
        g_dinv[i] = rsqrtf((float)(m + 1));
    }
}

__global__ __launch_bounds__(256) void prep_kernel(const float* __restrict__ x, const int* __restrict__ ei) {
    int gid = blockIdx.x * 256 + threadIdx.x;
    if (gid < EE / 4) {
        int4 s = ((const int4*)ei)[gid];
        int4 d = ((const int4*)(ei + EE))[gid];
        g_csrc[atomicAdd(&g_cur[d.x], 1)] = s.x;
        g_csrc[atomicAdd(&g_cur[d.y], 1)] = s.y;
        g_csrc[atomicAdd(&g_cur[d.z], 1)] = s.z;
        g_csrc[atomicAdd(&g_cur[d.w], 1)] = s.w;
    }
    int row = gid >> 2, part = gid & 3;
    int n = row >> 3, b = row & 7;
    const float4* xs = (const float4*)(x + ((size_t)b * NN + n) * 32 + part * 8);
    float4 v0 = xs[0], v1 = xs[1];
    float dn = g_dinv[n];
    union { unsigned short h[4]; uint2 v; } r;
    r.h[0] = q2(v0.x * dn, v0.y * dn);
    r.h[1] = q2(v0.z * dn, v0.w * dn);
    r.h[2] = q2(v1.x * dn, v1.y * dn);
    r.h[3] = q2(v1.z * dn, v1.w * dn);
    ((uint2*)g_bufA8)[gid] = r.v;
}

__device__ __forceinline__ void accv2(__half2* acc, uint2 v) {
    const __nv_fp8x2_storage_t* p = (const __nv_fp8x2_storage_t*)&v;
    #pragma unroll
    for (int i = 0; i < 4; ++i)
        acc[i] = __hadd2(acc[i], __half2(__nv_cvt_fp8x2_to_halfraw2(p[i], __NV_E4M3)));
}

// full warp gathers one node; lane owns bytes [8*lane, 8*lane+8) of the 256B row
__device__ __forceinline__ void gather_w(__half2* acc, const uint2* __restrict__ gin, int n, int lane) {
    const int* __restrict__ cs = g_csrc;
    #pragma unroll
    for (int i = 0; i < 4; ++i) acc[i] = __floats2half2_rn(0.f, 0.f);
    accv2(acc, gin[n * 32 + lane]);
    int j = g_rs[n], je = g_re[n];
    if (j + 4 <= je) {
        int s0 = __ldg(cs + j), s1 = __ldg(cs + j + 1), s2 = __ldg(cs + j + 2), s3 = __ldg(cs + j + 3);
        j += 4;
        while (j + 4 <= je) {
            uint2 v0 = gin[s0 * 32 + lane], v1 = gin[s1 * 32 + lane], v2 = gin[s2 * 32 + lane], v3 = gin[s3 * 32 + lane];
            s0 = __ldg(cs + j); s1 = __ldg(cs + j + 1); s2 = __ldg(cs + j + 2); s3 = __ldg(cs + j + 3);
            j += 4;
            accv2(acc, v0); accv2(acc, v1); accv2(acc, v2); accv2(acc, v3);
        }
        uint2 v0 = gin[s0 * 32 + lane], v1 = gin[s1 * 32 + lane], v2 = gin[s2 * 32 + lane], v3 = gin[s3 * 32 + lane];
        accv2(acc, v0); accv2(acc, v1); accv2(acc, v2); accv2(acc, v3);
    }
    for (; j < je; ++j) accv2(acc, gin[__ldg(cs + j) * 32 + lane]);
}

// warp w gathers nodes 2w, 2w+1 (uniform loops), stages rows 16w..16w+15, then wmma in place
__device__ __forceinline__ void gather_wmma(__half* sY, const __half* sW,
                                            const uint4* __restrict__ gin4, int n0, int t) {
    int lane = t & 31, w = t >> 5;
    const uint2* gin = (const uint2*)gin4;
    #pragma unroll
    for (int k = 0; k < 2; ++k) {
        int nl = 2 * w + k;
        __half2 acc[4];
        gather_w(acc, gin, n0 + nl, lane);
        int r = nl * 8 + (lane >> 2);
        *(uint4*)&sY[r * YSTR + (lane & 3) * 8] = *(uint4*)&acc[0];
    }
    __syncwarp();

    wmma::fragment<wmma::matrix_a, 16, 16, 16, __half, wmma::row_major> a0, a1;
    wmma::load_matrix_sync(a0, &sY[w * 16 * YSTR], YSTR);
    wmma::load_matrix_sync(a1, &sY[w * 16 * YSTR + 16], YSTR);

    wmma::fragment<wmma::accumulator, 16, 16, 16, __half> d0, d1;
    wmma::fill_fragment(d0, __float2half(0.f));
    wmma::fill_fragment(d1, __float2half(0.f));

    wmma::fragment<wmma::matrix_b, 16, 16, 16, __half, wmma::row_major> bf;
    wmma::load_matrix_sync(bf, &sW[0], YSTR);
    wmma::mma_sync(d0, a0, bf, d0);
    wmma::load_matrix_sync(bf, &sW[16], YSTR);
    wmma::mma_sync(d1, a0, bf, d1);
    wmma::load_matrix_sync(bf, &sW[16 * YSTR], YSTR);
    wmma::mma_sync(d0, a1, bf, d0);
    wmma::load_matrix_sync(bf, &sW[16 * YSTR + 16], YSTR);
    wmma::mma_sync(d1, a1, bf, d1);

    wmma::store_matrix_sync(&sY[w * 16 * YSTR], d0, YSTR, wmma::mem_row_major);
    wmma::store_matrix_sync(&sY[w * 16 * YSTR + 16], d1, YSTR, wmma::mem_row_major);
    __syncwarp();
}

__global__ __launch_bounds__(256) void g1_kernel(const float* __restrict__ W, const float* __restrict__ bias) {
    __shared__ __half sW[32 * YSTR];
    __shared__ __half sY[128 * YSTR];
    __shared__ __half2 sB2[16];
    int t = threadIdx.x;
    int n0 = blockIdx.x * 16;
    for (int i = t; i < 1024; i += 256) sW[(i >> 5) * YSTR + (i & 31)] = __float2half(W[i]);
    if (t < 16) sB2[t] = __floats2half2_rn(bias[2 * t], bias[2 * t + 1]);
    __syncthreads();

    gather_wmma(sY, sW, g_bufA8, n0, t);

    int r = t >> 1, hf = t & 1;
    int n = n0 + (r >> 3);
    __half2 dn2 = __float2half2_rn(g_dinv[n]);
    __half2 z2 = __floats2half2_rn(0.f, 0.f);
    const __half2* o = (const __half2*)&sY[r * YSTR + hf * 16];
    union { unsigned short h[8]; uint4 v; } q;
    #pragma unroll
    for (int i = 0; i < 8; ++i) {
        __half2 z = __hfma2(dn2, o[i], sB2[hf * 8 + i]);
        z = __hmul2(__hmax2(z, z2), dn2);
        q.h[i] = q2h(z);
    }
    g_bufB8[n0 * 16 + t] = q.v;
}

__global__ __launch_bounds__(256) void g2_kernel(const float* __restrict__ W, const float* __restrict__ bias, const float* __restrict__ W3) {
    __shared__ __half sW[32 * YSTR];
    __shared__ __half sY[128 * YSTR];
    __shared__ float sB[32];
    __shared__ float sW3[32];
    int t = threadIdx.x;
    int n0 = blockIdx.x * 16;
    for (int i = t; i < 1024; i += 256) sW[(i >> 5) * YSTR + (i & 31)] = __float2half(W[i]);
    if (t < 32) { sB[t] = bias[t]; sW3[t] = W3[t]; }
    __syncthreads();

    gather_wmma(sY, sW, g_bufB8, n0, t);

    int r = t >> 1, hf = t & 1, f0 = hf * 16;
    int n = n0 + (r >> 3), b = r & 7;
    float dn = g_dinv[n];
    const __half2* o = (const __half2*)&sY[r * YSTR + f0];
    float s = 0.f;
    #pragma unroll
    for (int i = 0; i < 8; ++i) {
        float2 f = __half22float2(o[i]);
        float h0 = fmaxf(fmaf(dn, f.x, sB[f0 + 2 * i]), 0.f);
        float h1 = fmaxf(fmaf(dn, f.y, sB[f0 + 2 * i + 1]), 0.f);
        s = fmaf(h0, sW3[f0 + 2 * i], s);
        s = fmaf(h1, sW3[f0 + 2 * i + 1], s);
    }
    s += __shfl_xor_sync(FM, s, 1);
    if (hf == 0) g_h3[n * 8 + b] = dn * s;
}

__global__ __launch_bounds__(256) void final_kernel(const float* __restrict__ b3, float* __restrict__ out) {
    int t = threadIdx.x, lane = t & 31, wid = t >> 5;
    int node = blockIdx.x * 128 + (t >> 1);
    int h = t & 1;
    const float4* __restrict__ h3v = (const float4*)g_h3;
    float p[4] = {0.f, 0.f, 0.f, 0.f};
    if (node < NN) {
        float4 a = h3v[node * 2 + h];
        int jb = g_rs[node], je = g_re[node];
        for (int j = jb; j < je; ++j) {
            float4 v = h3v[g_csrc[j] * 2 + h];
            a.x += v.x; a.y += v.y; a.z += v.z; a.w += v.w;
        }
        float dn = g_dinv[node], bb = b3[0];
        p[0] = 1.f / (1.f + expf(-fmaf(dn, a.x, bb)));
        p[1] = 1.f / (1.f + expf(-fmaf(dn, a.y, bb)));
        p[2] = 1.f / (1.f + expf(-fmaf(dn, a.z, bb)));
        p[3] = 1.f / (1.f + expf(-fmaf(dn, a.w, bb)));
    }
    for (int o = 2; o <= 16; o <<= 1) {
        #pragma unroll
        for (int i = 0; i < 4; ++i) p[i] += __shfl_xor_sync(FM, p[i], o);
    }
    __shared__ float sred[16][4];
    if (lane < 2) {
        #pragma unroll
        for (int i = 0; i < 4; ++i) sred[wid * 2 + lane][i] = p[i];
    }
    __syncthreads();
    if (t < 16) {
        float v[4];
        #pragma unroll
        for (int i = 0; i < 4; ++i) v[i] = sred[t][i];
        for (int o = 2; o <= 8; o <<= 1) {
            #pragma unroll
            for (int i = 0; i < 4; ++i) v[i] += __shfl_xor_sync(0x0000ffffu, v[i], o);
        }
        if (t < 2) {
            #pragma unroll
            for (int i = 0; i < 4; ++i) atomicAdd(&out[t * 4 + i], v[i]);
        }
    }
}

extern "C" void kernel_launch(void* const* d_in, const int* in_sizes, int n_in, void* d_out, int out_size) {
    const float* x  = (const float*)d_in[0];
    const float* W1 = (const float*)d_in[1];
    const float* b1 = (const float*)d_in[2];
    const float* W2 = (const float*)d_in[3];
    const float* b2 = (const float*)d_in[4];
    const float* W3 = (const float*)d_in[5];
    const float* b3 = (const float*)d_in[6];
    const int*   ei = (const int*)d_in[7];
    float* out = (float*)d_out;

    count_kernel<<<(EE / 4 + 255) / 256, 256>>>(ei, out);
    seg_kernel<<<(NN + 255) / 256, 256>>>();
    prep_kernel<<<NB * 4 / 256, 256>>>(x, ei);
    g1_kernel<<<NN / 16, 256>>>(W1, b1);
    g2_kernel<<<NN / 16, 256>>>(W2, b2, W3);
    final_kernel<<<(NN + 127) / 128, 256>>>(b3, out);
}